// round 13
// baseline (speedup 1.0000x reference)
#include <cuda_runtime.h>
#include <cuda_fp16.h>
#include <cstdint>

#define HID 128
#define NB 4
#define NSEQ 4096
#define ROWS_TOTAL (NB * NSEQ)   // 16384

// fp16 q/k/v scratch (device globals = sanctioned alloc-free scratch)
__device__ __half g_q[(size_t)ROWS_TOTAL * HID];
__device__ __half g_k[(size_t)ROWS_TOTAL * HID];
__device__ __half g_v[(size_t)ROWS_TOTAL * HID];

// ---------------------------------------------------------------------------
// helpers
// ---------------------------------------------------------------------------
__device__ __forceinline__ uint32_t smem_u32(const void* p) {
    uint32_t a;
    asm("{ .reg .u64 t; cvta.to.shared.u64 t, %1; cvt.u32.u64 %0, t; }" : "=r"(a) : "l"(p));
    return a;
}
__device__ __forceinline__ void ldsm4(uint32_t& r0, uint32_t& r1, uint32_t& r2, uint32_t& r3, uint32_t a) {
    asm volatile("ldmatrix.sync.aligned.m8n8.x4.shared.b16 {%0,%1,%2,%3}, [%4];"
                 : "=r"(r0), "=r"(r1), "=r"(r2), "=r"(r3) : "r"(a));
}
__device__ __forceinline__ void ldsm4t(uint32_t& r0, uint32_t& r1, uint32_t& r2, uint32_t& r3, uint32_t a) {
    asm volatile("ldmatrix.sync.aligned.m8n8.x4.trans.shared.b16 {%0,%1,%2,%3}, [%4];"
                 : "=r"(r0), "=r"(r1), "=r"(r2), "=r"(r3) : "r"(a));
}
// fp16 MMA, fp32 accumulate
__device__ __forceinline__ void mma16816h(float* c, const uint32_t* a, uint32_t b0, uint32_t b1) {
    asm volatile(
        "mma.sync.aligned.m16n8k16.row.col.f32.f16.f16.f32 "
        "{%0,%1,%2,%3}, {%4,%5,%6,%7}, {%8,%9}, {%0,%1,%2,%3};"
        : "+f"(c[0]), "+f"(c[1]), "+f"(c[2]), "+f"(c[3])
        : "r"(a[0]), "r"(a[1]), "r"(a[2]), "r"(a[3]), "r"(b0), "r"(b1));
}
__device__ __forceinline__ void cpasync16(uint32_t s, const void* g) {
    asm volatile("cp.async.cg.shared.global [%0], [%1], 16;" :: "r"(s), "l"(g));
}
#define CP_COMMIT() asm volatile("cp.async.commit_group;" ::: "memory")
#define CP_WAIT1()  asm volatile("cp.async.wait_group 1;" ::: "memory")

__device__ __forceinline__ uint32_t ex2h2(uint32_t x) {
    uint32_t y;
    asm("ex2.approx.f16x2 %0, %1;" : "=r"(y) : "r"(x));
    return y;
}
__device__ __forceinline__ uint32_t pack_h2(float a, float b) {
    __half2 v = __floats2half2_rn(a, b);
    return *reinterpret_cast<uint32_t*>(&v);
}
// smem tile layout: row pitch 256B (128 b16 elems), 16B chunks xor-swizzled
__device__ __forceinline__ uint32_t swoff(int row, int c) {
    return (uint32_t)(row * 256 + ((c ^ (row & 7)) << 4));
}

// log2(e)/sqrt(128): folded into q so attention uses ex2 directly.
#define PSQ ((float)(1.4426950408889634 / 11.313708498984761))
#define H2_ONES 0x3C003C00u   // half2(1.0, 1.0)

// ---------------------------------------------------------------------------
// Kernel 1: QKV projection via single-combo fp16 mma.sync (unchanged from R11).
// grid (128 row-tiles, 3 weights), 256 threads, 64KB smem.
// ---------------------------------------------------------------------------
#define QX_OFF 0
#define QW_OFF 32768

__global__ __launch_bounds__(256, 1) void qkv_h(const float* __restrict__ x,
                                                const float* __restrict__ Wq,
                                                const float* __restrict__ Wk,
                                                const float* __restrict__ Wv) {
    extern __shared__ char smc[];
    const uint32_t smb = smem_u32(smc);
    const int t = threadIdx.x, w = t >> 5, l = t & 31;
    const int wsel = blockIdx.y;
    const int row0 = blockIdx.x * 128;

    const float* W = (wsel == 0) ? Wq : ((wsel == 1) ? Wk : Wv);
    __half* outA = (wsel == 0) ? g_q : ((wsel == 1) ? g_k : g_v);
    const float ps = (wsel == 0) ? PSQ : 1.0f;

    const float4* xg = (const float4*)(x + (size_t)row0 * HID);
    const float4* Wg = (const float4*)W;
    for (int i = t; i < 2048; i += 256) {
        int row = i >> 4, c = i & 15;
        uint32_t d = swoff(row, c);
        float4 a0 = xg[2 * i], a1 = xg[2 * i + 1];
        uint4 hx = make_uint4(pack_h2(a0.x, a0.y), pack_h2(a0.z, a0.w),
                              pack_h2(a1.x, a1.y), pack_h2(a1.z, a1.w));
        *(uint4*)(smc + QX_OFF + d) = hx;
        float4 b0 = Wg[2 * i], b1 = Wg[2 * i + 1];
        uint4 hw = make_uint4(pack_h2(b0.x, b0.y), pack_h2(b0.z, b0.w),
                              pack_h2(b1.x, b1.y), pack_h2(b1.z, b1.w));
        *(uint4*)(smc + QW_OFF + d) = hw;
    }
    __syncthreads();

    uint32_t qf[8][4];
    {
        const int rowq = w * 16 + (((l >> 3) & 1) << 3) + (l & 7);
        const int cadd = l >> 4;
#pragma unroll
        for (int ks = 0; ks < 8; ks++) {
            uint32_t a = smb + QX_OFF + swoff(rowq, ks * 2 + cadd);
            ldsm4(qf[ks][0], qf[ks][1], qf[ks][2], qf[ks][3], a);
        }
    }

    const int krow = ((l >> 4) << 3) + (l & 7);
    const int kc   = (l >> 3) & 1;

    float acc[16][4];
#pragma unroll
    for (int i = 0; i < 16; i++)
#pragma unroll
        for (int j = 0; j < 4; j++) acc[i][j] = 0.f;

#pragma unroll
    for (int ks = 0; ks < 8; ks++) {
#pragma unroll
        for (int g = 0; g < 2; g++) {
            uint32_t kb[4][4];
#pragma unroll
            for (int j = 0; j < 4; j++) {
                uint32_t ka = smb + QW_OFF + swoff((g * 4 + j) * 16 + krow, ks * 2 + kc);
                ldsm4(kb[j][0], kb[j][1], kb[j][2], kb[j][3], ka);
            }
#pragma unroll
            for (int j = 0; j < 4; j++) mma16816h(acc[2 * (g * 4 + j)],     qf[ks], kb[j][0], kb[j][1]);
#pragma unroll
            for (int j = 0; j < 4; j++) mma16816h(acc[2 * (g * 4 + j) + 1], qf[ks], kb[j][2], kb[j][3]);
        }
    }

    const int r0 = row0 + w * 16 + (l >> 2);
    const int cb = (l & 3) * 2;
#pragma unroll
    for (int nt = 0; nt < 16; nt++) {
        uint32_t h0 = pack_h2(acc[nt][0] * ps, acc[nt][1] * ps);
        uint32_t h1 = pack_h2(acc[nt][2] * ps, acc[nt][3] * ps);
        size_t o0 = (size_t)r0 * HID + cb + nt * 8;
        size_t o1 = o0 + 8 * HID;
        *(uint32_t*)(outA + o0) = h0;
        *(uint32_t*)(outA + o1) = h1;
    }
}

// ---------------------------------------------------------------------------
// Kernel 2: fp16 flash attention, 512 threads / 16 warps (4 per SMSP).
// Warp = (rowgroup rg 0-7, keyhalf kh 0-1): 16 q-rows x 32 of 64 keys.
// Partial O / row-sums reduced across keyhalf pairs via smem at epilogue.
// grid (32 q-tiles, 4 batches), 64KB smem (+2KB lacc region).
// ---------------------------------------------------------------------------
#define STAGE_BYTES 32768
#define V_OFF 16384
#define SL_OFF 65536
#define ATTN_SMEM_T (65536 + 2048)

__global__ __launch_bounds__(512, 1) void attn_mma(float* __restrict__ out) {
    extern __shared__ char smc[];
    const uint32_t smb = smem_u32(smc);
    const int t = threadIdx.x, w = t >> 5, l = t & 31;
    const int rg = w >> 1, kh = w & 1;
    const int b = blockIdx.y, q0 = blockIdx.x * 128;

    const uint4* gq = (const uint4*)(g_q + ((size_t)b * NSEQ + q0) * HID);
    const uint4* gk = (const uint4*)(g_k + (size_t)b * NSEQ * HID);
    const uint4* gv = (const uint4*)(g_v + (size_t)b * NSEQ * HID);

    // ---- stage Q into smem (stage-0/1 scratch), ldmatrix to regs ----
    for (int i = t; i < 2048; i += 512) {
        int row = i >> 4, c = i & 15;
        *(uint4*)(smc + swoff(row, c)) = gq[i];
    }
    __syncthreads();

    uint32_t qf[8][4];
    {
        const int rowq = rg * 16 + (((l >> 3) & 1) << 3) + (l & 7);
        const int cadd = l >> 4;
#pragma unroll
        for (int ks = 0; ks < 8; ks++) {
            uint32_t a = smb + swoff(rowq, ks * 2 + cadd);
            ldsm4(qf[ks][0], qf[ks][1], qf[ks][2], qf[ks][3], a);
        }
    }
    __syncthreads();   // Q-frag reads complete before prefetch overwrites

    float oacc[16][4];
#pragma unroll
    for (int i = 0; i < 16; i++)
#pragma unroll
        for (int j = 0; j < 4; j++) oacc[i][j] = 0.f;
    float lacc[4] = {0.f, 0.f, 0.f, 0.f};   // partial row sums (this keyhalf)

    // prefetch tile 0 into stage 0
    {
#pragma unroll
        for (int i = 0; i < 2; i++) {
            int lin = i * 512 + t;
            int row = lin >> 4, c = lin & 15;
            uint32_t d = swoff(row, c);
            size_t gidx = (size_t)row * 16 + c;
            cpasync16(smb + d, gk + gidx);
            cpasync16(smb + V_OFF + d, gv + gidx);
        }
    }
    CP_COMMIT();

    const int krow = ((l >> 4) << 3) + (l & 7);
    const int kc   = (l >> 3) & 1;
    const int vrow = (((l >> 3) & 1) << 3) + (l & 7);
    const int vc   = l >> 4;
    const int kb0  = kh * 2;                 // first 16-key block of this keyhalf

    for (int kt = 0; kt < 64; kt++) {
        __syncthreads();
        {
            const int ktn = (kt + 1 < 64) ? kt + 1 : 63;
            const uint32_t stn = smb + ((kt + 1) & 1) * STAGE_BYTES;
            const int key0 = ktn * 64;
#pragma unroll
            for (int i = 0; i < 2; i++) {
                int lin = i * 512 + t;
                int row = lin >> 4, c = lin & 15;
                uint32_t d = swoff(row, c);
                size_t gidx = (size_t)(key0 + row) * 16 + c;
                cpasync16(stn + d, gk + gidx);
                cpasync16(stn + V_OFF + d, gv + gidx);
            }
        }
        CP_COMMIT();
        CP_WAIT1();
        __syncthreads();

        const uint32_t st = smb + (kt & 1) * STAGE_BYTES;

        // ---- S = Q K^T over this keyhalf's 32 keys ----
        float sc[4][4];
#pragma unroll
        for (int i = 0; i < 4; i++)
#pragma unroll
            for (int j = 0; j < 4; j++) sc[i][j] = 0.f;

#pragma unroll
        for (int ks = 0; ks < 8; ks++) {
            uint32_t kb[2][4];
#pragma unroll
            for (int j = 0; j < 2; j++) {
                uint32_t ka = st + swoff((kb0 + j) * 16 + krow, ks * 2 + kc);
                ldsm4(kb[j][0], kb[j][1], kb[j][2], kb[j][3], ka);
            }
#pragma unroll
            for (int j = 0; j < 2; j++) mma16816h(sc[2 * j],     qf[ks], kb[j][0], kb[j][1]);
#pragma unroll
            for (int j = 0; j < 2; j++) mma16816h(sc[2 * j + 1], qf[ks], kb[j][2], kb[j][3]);
        }

        // ---- softmax: p = 2^s in half2 MUFU; C->A fragment identity ----
        uint32_t ph[2][4];
#pragma unroll
        for (int j = 0; j < 2; j++) {
            ph[j][0] = ex2h2(pack_h2(sc[2 * j][0],     sc[2 * j][1]));
            ph[j][1] = ex2h2(pack_h2(sc[2 * j][2],     sc[2 * j][3]));
            ph[j][2] = ex2h2(pack_h2(sc[2 * j + 1][0], sc[2 * j + 1][1]));
            ph[j][3] = ex2h2(pack_h2(sc[2 * j + 1][2], sc[2 * j + 1][3]));
            mma16816h(lacc, ph[j], H2_ONES, H2_ONES);
        }

        // ---- O += P V over this keyhalf's 32 keys ----
#pragma unroll
        for (int j = 0; j < 2; j++) {
#pragma unroll
            for (int npc = 0; npc < 2; npc++) {
                uint32_t vb[4][4];
#pragma unroll
                for (int jj = 0; jj < 4; jj++) {
                    uint32_t va = st + V_OFF + swoff((kb0 + j) * 16 + vrow, (npc * 4 + jj) * 2 + vc);
                    ldsm4t(vb[jj][0], vb[jj][1], vb[jj][2], vb[jj][3], va);
                }
#pragma unroll
                for (int jj = 0; jj < 4; jj++) mma16816h(oacc[2 * (npc * 4 + jj)],     ph[j], vb[jj][0], vb[jj][1]);
#pragma unroll
                for (int jj = 0; jj < 4; jj++) mma16816h(oacc[2 * (npc * 4 + jj) + 1], ph[j], vb[jj][2], vb[jj][3]);
            }
        }
    }

    // ---- epilogue: reduce keyhalf partials via smem, normalize, store ----
    __syncthreads();   // done reading stages; reuse as reduction buffer
    if (kh == 1) {
        float4* dst = (float4*)(smc + rg * 8192);
#pragma unroll
        for (int i = 0; i < 16; i++)
            dst[i * 32 + l] = make_float4(oacc[i][0], oacc[i][1], oacc[i][2], oacc[i][3]);
        float* ld = (float*)(smc + SL_OFF);
        ld[rg * 64 + l * 2]     = lacc[0];
        ld[rg * 64 + l * 2 + 1] = lacc[2];
    }
    __syncthreads();
    if (kh == 0) {
        const float4* src = (const float4*)(smc + rg * 8192);
        const float* ld = (const float*)(smc + SL_OFF);
        const float inv0 = 1.f / (lacc[0] + ld[rg * 64 + l * 2]);
        const float inv1 = 1.f / (lacc[2] + ld[rg * 64 + l * 2 + 1]);

        const int r0 = q0 + rg * 16 + (l >> 2);
        float* o0 = out + ((size_t)b * NSEQ + r0) * HID + (l & 3) * 2;
        float* o1 = o0 + 8 * HID;
#pragma unroll
        for (int nt = 0; nt < 16; nt++) {
            float4 v = src[nt * 32 + l];
            *(float2*)(o0 + nt * 8) = make_float2((oacc[nt][0] + v.x) * inv0,
                                                  (oacc[nt][1] + v.y) * inv0);
            *(float2*)(o1 + nt * 8) = make_float2((oacc[nt][2] + v.z) * inv1,
                                                  (oacc[nt][3] + v.w) * inv1);
        }
    }
}

// ---------------------------------------------------------------------------
extern "C" void kernel_launch(void* const* d_in, const int* in_sizes, int n_in,
                              void* d_out, int out_size) {
    const float* x  = (const float*)d_in[0];
    const float* Wq = (const float*)d_in[1];
    const float* Wk = (const float*)d_in[2];
    const float* Wv = (const float*)d_in[3];
    float* out = (float*)d_out;

    const int QKV_SMEM = 65536;   // X 32KB + W 32KB

    cudaFuncSetAttribute(qkv_h,    cudaFuncAttributeMaxDynamicSharedMemorySize, QKV_SMEM);
    cudaFuncSetAttribute(attn_mma, cudaFuncAttributeMaxDynamicSharedMemorySize, ATTN_SMEM_T);

    qkv_h<<<dim3(128, 3), 256, QKV_SMEM>>>(x, Wq, Wk, Wv);
    attn_mma<<<dim3(32, 4), 512, ATTN_SMEM_T>>>(out);
}

// round 14
// speedup vs baseline: 1.2338x; 1.2338x over previous
#include <cuda_runtime.h>
#include <cuda_fp16.h>
#include <cstdint>

#define HID 128
#define NB 4
#define NSEQ 4096
#define ROWS_TOTAL (NB * NSEQ)   // 16384

// fp16 q/k/v scratch (device globals = sanctioned alloc-free scratch)
__device__ __half g_q[(size_t)ROWS_TOTAL * HID];
__device__ __half g_k[(size_t)ROWS_TOTAL * HID];
__device__ __half g_v[(size_t)ROWS_TOTAL * HID];

// ---------------------------------------------------------------------------
// helpers
// ---------------------------------------------------------------------------
__device__ __forceinline__ uint32_t smem_u32(const void* p) {
    uint32_t a;
    asm("{ .reg .u64 t; cvta.to.shared.u64 t, %1; cvt.u32.u64 %0, t; }" : "=r"(a) : "l"(p));
    return a;
}
__device__ __forceinline__ void ldsm4(uint32_t& r0, uint32_t& r1, uint32_t& r2, uint32_t& r3, uint32_t a) {
    asm volatile("ldmatrix.sync.aligned.m8n8.x4.shared.b16 {%0,%1,%2,%3}, [%4];"
                 : "=r"(r0), "=r"(r1), "=r"(r2), "=r"(r3) : "r"(a));
}
__device__ __forceinline__ void ldsm4t(uint32_t& r0, uint32_t& r1, uint32_t& r2, uint32_t& r3, uint32_t a) {
    asm volatile("ldmatrix.sync.aligned.m8n8.x4.trans.shared.b16 {%0,%1,%2,%3}, [%4];"
                 : "=r"(r0), "=r"(r1), "=r"(r2), "=r"(r3) : "r"(a));
}
// fp16 MMA, fp32 accumulate
__device__ __forceinline__ void mma16816h(float* c, const uint32_t* a, uint32_t b0, uint32_t b1) {
    asm volatile(
        "mma.sync.aligned.m16n8k16.row.col.f32.f16.f16.f32 "
        "{%0,%1,%2,%3}, {%4,%5,%6,%7}, {%8,%9}, {%0,%1,%2,%3};"
        : "+f"(c[0]), "+f"(c[1]), "+f"(c[2]), "+f"(c[3])
        : "r"(a[0]), "r"(a[1]), "r"(a[2]), "r"(a[3]), "r"(b0), "r"(b1));
}
__device__ __forceinline__ void cpasync16(uint32_t s, const void* g) {
    asm volatile("cp.async.cg.shared.global [%0], [%1], 16;" :: "r"(s), "l"(g));
}
#define CP_COMMIT() asm volatile("cp.async.commit_group;" ::: "memory")
#define CP_WAIT2()  asm volatile("cp.async.wait_group 2;" ::: "memory")

__device__ __forceinline__ uint32_t ex2h2(uint32_t x) {
    uint32_t y;
    asm("ex2.approx.f16x2 %0, %1;" : "=r"(y) : "r"(x));
    return y;
}
__device__ __forceinline__ uint32_t pack_h2(float a, float b) {
    __half2 v = __floats2half2_rn(a, b);
    return *reinterpret_cast<uint32_t*>(&v);
}
// smem tile layout: row pitch 256B (128 b16 elems), 16B chunks xor-swizzled
__device__ __forceinline__ uint32_t swoff(int row, int c) {
    return (uint32_t)(row * 256 + ((c ^ (row & 7)) << 4));
}

// log2(e)/sqrt(128): folded into q so attention uses ex2 directly.
#define PSQ ((float)(1.4426950408889634 / 11.313708498984761))
#define H2_ONES 0x3C003C00u   // half2(1.0, 1.0)

// ---------------------------------------------------------------------------
// Kernel 1: fused QKV projection (x staged once; Wq/Wk/Wv resident in smem).
// grid (128 row-tiles), 256 threads, 128KB smem.
// ---------------------------------------------------------------------------
#define FX_OFF 0
#define FW_OFF 32768   // + wsel * 32768

__global__ __launch_bounds__(256, 1) void qkv_h(const float* __restrict__ x,
                                                const float* __restrict__ Wq,
                                                const float* __restrict__ Wk,
                                                const float* __restrict__ Wv) {
    extern __shared__ char smc[];
    const uint32_t smb = smem_u32(smc);
    const int t = threadIdx.x, w = t >> 5, l = t & 31;
    const int row0 = blockIdx.x * 128;

    const float* Ws[3] = {Wq, Wk, Wv};

    // ---- stage x tile + all three W as fp16 (swizzled) ----
    const float4* xg = (const float4*)(x + (size_t)row0 * HID);
    for (int i = t; i < 2048; i += 256) {
        int row = i >> 4, c = i & 15;
        uint32_t d = swoff(row, c);
        float4 a0 = xg[2 * i], a1 = xg[2 * i + 1];
        *(uint4*)(smc + FX_OFF + d) =
            make_uint4(pack_h2(a0.x, a0.y), pack_h2(a0.z, a0.w),
                       pack_h2(a1.x, a1.y), pack_h2(a1.z, a1.w));
#pragma unroll
        for (int wsel = 0; wsel < 3; wsel++) {
            const float4* Wg = (const float4*)Ws[wsel];
            float4 b0 = Wg[2 * i], b1 = Wg[2 * i + 1];
            *(uint4*)(smc + FW_OFF + wsel * 32768 + d) =
                make_uint4(pack_h2(b0.x, b0.y), pack_h2(b0.z, b0.w),
                           pack_h2(b1.x, b1.y), pack_h2(b1.z, b1.w));
        }
    }
    __syncthreads();

    uint32_t qf[8][4];
    {
        const int rowq = w * 16 + (((l >> 3) & 1) << 3) + (l & 7);
        const int cadd = l >> 4;
#pragma unroll
        for (int ks = 0; ks < 8; ks++) {
            uint32_t a = smb + FX_OFF + swoff(rowq, ks * 2 + cadd);
            ldsm4(qf[ks][0], qf[ks][1], qf[ks][2], qf[ks][3], a);
        }
    }

    const int krow = ((l >> 4) << 3) + (l & 7);
    const int kc   = (l >> 3) & 1;
    const int r0   = row0 + w * 16 + (l >> 2);
    const int cb   = (l & 3) * 2;

#pragma unroll
    for (int wsel = 0; wsel < 3; wsel++) {
        const uint32_t wbase = smb + FW_OFF + wsel * 32768;
        float acc[16][4];
#pragma unroll
        for (int i = 0; i < 16; i++)
#pragma unroll
            for (int j = 0; j < 4; j++) acc[i][j] = 0.f;

#pragma unroll
        for (int ks = 0; ks < 8; ks++) {
#pragma unroll
            for (int g = 0; g < 2; g++) {
                uint32_t kb[4][4];
#pragma unroll
                for (int j = 0; j < 4; j++) {
                    uint32_t ka = wbase + swoff((g * 4 + j) * 16 + krow, ks * 2 + kc);
                    ldsm4(kb[j][0], kb[j][1], kb[j][2], kb[j][3], ka);
                }
#pragma unroll
                for (int j = 0; j < 4; j++) mma16816h(acc[2 * (g * 4 + j)],     qf[ks], kb[j][0], kb[j][1]);
#pragma unroll
                for (int j = 0; j < 4; j++) mma16816h(acc[2 * (g * 4 + j) + 1], qf[ks], kb[j][2], kb[j][3]);
            }
        }

        __half* outA = (wsel == 0) ? g_q : ((wsel == 1) ? g_k : g_v);
        const float ps = (wsel == 0) ? PSQ : 1.0f;
#pragma unroll
        for (int nt = 0; nt < 16; nt++) {
            uint32_t h0 = pack_h2(acc[nt][0] * ps, acc[nt][1] * ps);
            uint32_t h1 = pack_h2(acc[nt][2] * ps, acc[nt][3] * ps);
            size_t o0 = (size_t)r0 * HID + cb + nt * 8;
            size_t o1 = o0 + 8 * HID;
            *(uint32_t*)(outA + o0) = h0;
            *(uint32_t*)(outA + o1) = h1;
        }
    }
}

// ---------------------------------------------------------------------------
// Kernel 2: fp16 flash attention, 4-stage cp.async pipeline (distance-2
// prefetch, ONE barrier per tile). 256 threads, 128KB smem.
// ---------------------------------------------------------------------------
#define STAGE_BYTES 32768
#define V_OFF 16384
#define NTILE 64

__global__ __launch_bounds__(256, 1) void attn_mma(float* __restrict__ out) {
    extern __shared__ char smc[];
    const uint32_t smb = smem_u32(smc);
    const int t = threadIdx.x, w = t >> 5, l = t & 31;
    const int b = blockIdx.y, q0 = blockIdx.x * 128;

    const uint4* gq = (const uint4*)(g_q + ((size_t)b * NSEQ + q0) * HID);
    const uint4* gk = (const uint4*)(g_k + (size_t)b * NSEQ * HID);
    const uint4* gv = (const uint4*)(g_v + (size_t)b * NSEQ * HID);

    // ---- stage Q into stage-0 region, ldmatrix to regs ----
    for (int i = t; i < 2048; i += 256) {
        int row = i >> 4, c = i & 15;
        *(uint4*)(smc + swoff(row, c)) = gq[i];
    }
    __syncthreads();

    uint32_t qf[8][4];
    {
        const int rowq = w * 16 + (((l >> 3) & 1) << 3) + (l & 7);
        const int cadd = l >> 4;
#pragma unroll
        for (int ks = 0; ks < 8; ks++) {
            uint32_t a = smb + swoff(rowq, ks * 2 + cadd);
            ldsm4(qf[ks][0], qf[ks][1], qf[ks][2], qf[ks][3], a);
        }
    }
    __syncthreads();   // Q-frag reads complete before prefetch overwrites

    float oacc[16][4];
#pragma unroll
    for (int i = 0; i < 16; i++)
#pragma unroll
        for (int j = 0; j < 4; j++) oacc[i][j] = 0.f;
    float lacc[4] = {0.f, 0.f, 0.f, 0.f};

    // ---- prologue: prefetch tile 0 -> stage 0, tile 1 -> stage 1 ----
#pragma unroll
    for (int pre = 0; pre < 2; pre++) {
        const uint32_t dst = smb + pre * STAGE_BYTES;
#pragma unroll
        for (int i = 0; i < 4; i++) {
            int lin = i * 256 + t;
            int row = lin >> 4, c = lin & 15;
            uint32_t d = swoff(row, c);
            size_t gidx = (size_t)(pre * 64 + row) * 16 + c;
            cpasync16(dst + d, gk + gidx);
            cpasync16(dst + V_OFF + d, gv + gidx);
        }
        CP_COMMIT();
    }

    const int krow = ((l >> 4) << 3) + (l & 7);
    const int kc   = (l >> 3) & 1;
    const int vrow = (((l >> 3) & 1) << 3) + (l & 7);
    const int vc   = l >> 4;

    for (int kt = 0; kt < NTILE; kt++) {
        // issue G(kt): tile kt+2 -> stage (kt+2)&3 (stage of tile kt-2;
        // the barrier below collectively orders compute(kt-2) before this)
        {
            const int ktn = (kt + 2 < NTILE) ? kt + 2 : NTILE - 1;
            const uint32_t stn = smb + (uint32_t)((kt + 2) & 3) * STAGE_BYTES;
            const int key0 = ktn * 64;
#pragma unroll
            for (int i = 0; i < 4; i++) {
                int lin = i * 256 + t;
                int row = lin >> 4, c = lin & 15;
                uint32_t d = swoff(row, c);
                size_t gidx = (size_t)(key0 + row) * 16 + c;
                cpasync16(stn + d, gk + gidx);
                cpasync16(stn + V_OFF + d, gv + gidx);
            }
        }
        CP_COMMIT();
        CP_WAIT2();        // tile kt's group (G(kt-2)) complete
        __syncthreads();   // single barrier per tile

        const uint32_t st = smb + (uint32_t)(kt & 3) * STAGE_BYTES;

        // ---- S = Q K^T : single fp16 combo, step-major ----
        float sc[8][4];
#pragma unroll
        for (int i = 0; i < 8; i++)
#pragma unroll
            for (int j = 0; j < 4; j++) sc[i][j] = 0.f;

#pragma unroll
        for (int ks = 0; ks < 8; ks++) {
            uint32_t kb[4][4];
#pragma unroll
            for (int j = 0; j < 4; j++) {
                uint32_t ka = st + swoff(j * 16 + krow, ks * 2 + kc);
                ldsm4(kb[j][0], kb[j][1], kb[j][2], kb[j][3], ka);
            }
#pragma unroll
            for (int j = 0; j < 4; j++) mma16816h(sc[2 * j],     qf[ks], kb[j][0], kb[j][1]);
#pragma unroll
            for (int j = 0; j < 4; j++) mma16816h(sc[2 * j + 1], qf[ks], kb[j][2], kb[j][3]);
        }

        // ---- softmax: p = 2^s in half2 MUFU ----
        uint32_t ph8[8][2];
#pragma unroll
        for (int i = 0; i < 8; i++) {
            ph8[i][0] = ex2h2(pack_h2(sc[i][0], sc[i][1]));
            ph8[i][1] = ex2h2(pack_h2(sc[i][2], sc[i][3]));
        }

        // ---- O += P V ; row sums via ones-MMA ----
#pragma unroll
        for (int ks2 = 0; ks2 < 4; ks2++) {
            uint32_t ph[4] = {ph8[2 * ks2][0], ph8[2 * ks2][1],
                              ph8[2 * ks2 + 1][0], ph8[2 * ks2 + 1][1]};
            mma16816h(lacc, ph, H2_ONES, H2_ONES);
#pragma unroll
            for (int npc = 0; npc < 2; npc++) {
                uint32_t vb[4][4];
#pragma unroll
                for (int j = 0; j < 4; j++) {
                    uint32_t va = st + V_OFF + swoff(ks2 * 16 + vrow, (npc * 4 + j) * 2 + vc);
                    ldsm4t(vb[j][0], vb[j][1], vb[j][2], vb[j][3], va);
                }
#pragma unroll
                for (int j = 0; j < 4; j++) mma16816h(oacc[2 * (npc * 4 + j)],     ph, vb[j][0], vb[j][1]);
#pragma unroll
                for (int j = 0; j < 4; j++) mma16816h(oacc[2 * (npc * 4 + j) + 1], ph, vb[j][2], vb[j][3]);
            }
        }
    }

    // ---- epilogue ----
    const float inv0 = 1.f / lacc[0], inv1 = 1.f / lacc[2];

    const int r0 = q0 + w * 16 + (l >> 2);
    float* o0 = out + ((size_t)b * NSEQ + r0) * HID + (l & 3) * 2;
    float* o1 = o0 + 8 * HID;
#pragma unroll
    for (int nt = 0; nt < 16; nt++) {
        *(float2*)(o0 + nt * 8) = make_float2(oacc[nt][0] * inv0, oacc[nt][1] * inv0);
        *(float2*)(o1 + nt * 8) = make_float2(oacc[nt][2] * inv1, oacc[nt][3] * inv1);
    }
}

// ---------------------------------------------------------------------------
extern "C" void kernel_launch(void* const* d_in, const int* in_sizes, int n_in,
                              void* d_out, int out_size) {
    const float* x  = (const float*)d_in[0];
    const float* Wq = (const float*)d_in[1];
    const float* Wk = (const float*)d_in[2];
    const float* Wv = (const float*)d_in[3];
    float* out = (float*)d_out;

    const int QKV_SMEM  = 131072;   // x 32KB + 3 x W 32KB
    const int ATTN_SMEM = 4 * STAGE_BYTES;   // 128KB

    cudaFuncSetAttribute(qkv_h,    cudaFuncAttributeMaxDynamicSharedMemorySize, QKV_SMEM);
    cudaFuncSetAttribute(attn_mma, cudaFuncAttributeMaxDynamicSharedMemorySize, ATTN_SMEM);

    qkv_h<<<dim3(128), 256, QKV_SMEM>>>(x, Wq, Wk, Wv);
    attn_mma<<<dim3(32, 4), 256, ATTN_SMEM>>>(out);
}